// round 6
// baseline (speedup 1.0000x reference)
#include <cuda_runtime.h>
#include <cuda_fp16.h>
#include <cstdint>
#include <cstddef>

// BinaryLinear: y = x @ sign(W)^T + b
//   x: [32768, 1024] f32, W: [1024, 1024] f32, b: [1024] f32, y: [32768, 1024] f32
// Strategy: sign(W) in {-1,0,+1} is exact in fp16; convert x -> fp16 (rel err ~2.8e-4
// accumulated, safely < 1e-3), then fp16 tensor-core GEMM with fp32 accumulate.

static constexpr int M_TOK = 32768;
static constexpr int N_OUT = 1024;
static constexpr int K_IN  = 1024;

static constexpr int BM = 128, BN = 128, BK = 32;
static constexpr int PITCH = 40;             // halves per smem row (80B) -> conflict-free ldmatrix
static constexpr int NKT = K_IN / BK;        // 32 k-tiles

// Scratch (allocation-free workaround): fp16 x and fp16 sign(W)
__device__ __half g_xh[(size_t)M_TOK * K_IN];   // 64 MB
__device__ __half g_ws[(size_t)N_OUT * K_IN];   // 2 MB

// ---------------------------------------------------------------------------
// Conversion kernels
// ---------------------------------------------------------------------------
__global__ void convert_x_kernel(const float* __restrict__ x) {
    size_t i = ((size_t)blockIdx.x * blockDim.x + threadIdx.x) * 4;
    float4 v = *reinterpret_cast<const float4*>(x + i);
    __half2* dst = reinterpret_cast<__half2*>(g_xh + i);
    dst[0] = __floats2half2_rn(v.x, v.y);
    dst[1] = __floats2half2_rn(v.z, v.w);
}

__global__ void convert_w_kernel(const float* __restrict__ w) {
    size_t i = ((size_t)blockIdx.x * blockDim.x + threadIdx.x) * 4;
    float4 v = *reinterpret_cast<const float4*>(w + i);
    float s0 = (float)((v.x > 0.f) - (v.x < 0.f));
    float s1 = (float)((v.y > 0.f) - (v.y < 0.f));
    float s2 = (float)((v.z > 0.f) - (v.z < 0.f));
    float s3 = (float)((v.w > 0.f) - (v.w < 0.f));
    __half2* dst = reinterpret_cast<__half2*>(g_ws + i);
    dst[0] = __floats2half2_rn(s0, s1);
    dst[1] = __floats2half2_rn(s2, s3);
}

// ---------------------------------------------------------------------------
// GEMM kernel: 128x128x32 CTA tile, 8 warps (4x2), warp tile 32x64,
// mma.sync.m16n8k16 f16->f32, cp.async double buffer.
// ---------------------------------------------------------------------------
__device__ __forceinline__ void cp_async16(uint32_t smem, const void* gmem) {
    asm volatile("cp.async.cg.shared.global [%0], [%1], 16;" :: "r"(smem), "l"(gmem));
}

#define MMA_16816(d, a, b)                                                    \
    asm volatile(                                                             \
        "mma.sync.aligned.m16n8k16.row.col.f32.f16.f16.f32 "                  \
        "{%0,%1,%2,%3}, {%4,%5,%6,%7}, {%8,%9}, {%0,%1,%2,%3};"               \
        : "+f"((d)[0]), "+f"((d)[1]), "+f"((d)[2]), "+f"((d)[3])              \
        : "r"((a)[0]), "r"((a)[1]), "r"((a)[2]), "r"((a)[3]),                 \
          "r"((b)[0]), "r"((b)[1]))

__global__ __launch_bounds__(256, 2)
void gemm_kernel(const float* __restrict__ bias, float* __restrict__ out) {
    __shared__ __half sA[2][BM * PITCH];
    __shared__ __half sB[2][BN * PITCH];

    const int tid    = threadIdx.x;
    const int lane   = tid & 31;
    const int warp   = tid >> 5;
    const int warp_m = warp & 3;   // 4 warps along M
    const int warp_n = warp >> 2;  // 2 warps along N
    const int bm = blockIdx.y * BM;
    const int bn = blockIdx.x * BN;

    const __half* gA = g_xh + (size_t)bm * K_IN;
    const __half* gB = g_ws + (size_t)bn * K_IN;

    // Global->smem load mapping: 512 chunks of 16B (128 rows x 4 chunks),
    // each thread moves 2 chunks for A and 2 for B.
    const int c0 = tid,       r0 = c0 >> 2, col0 = (c0 & 3) * 8;
    const int c1 = tid + 256, r1 = c1 >> 2, col1 = (c1 & 3) * 8;

    float acc[2][8][4];
#pragma unroll
    for (int mi = 0; mi < 2; mi++)
#pragma unroll
        for (int ni = 0; ni < 8; ni++)
#pragma unroll
            for (int q = 0; q < 4; q++) acc[mi][ni][q] = 0.f;

#define PREFETCH(buf, k0)                                                                      \
    do {                                                                                       \
        cp_async16((uint32_t)__cvta_generic_to_shared(&sA[buf][r0 * PITCH + col0]),            \
                   gA + (size_t)r0 * K_IN + (k0) + col0);                                      \
        cp_async16((uint32_t)__cvta_generic_to_shared(&sA[buf][r1 * PITCH + col1]),            \
                   gA + (size_t)r1 * K_IN + (k0) + col1);                                      \
        cp_async16((uint32_t)__cvta_generic_to_shared(&sB[buf][r0 * PITCH + col0]),            \
                   gB + (size_t)r0 * K_IN + (k0) + col0);                                      \
        cp_async16((uint32_t)__cvta_generic_to_shared(&sB[buf][r1 * PITCH + col1]),            \
                   gB + (size_t)r1 * K_IN + (k0) + col1);                                      \
    } while (0)

    PREFETCH(0, 0);
    asm volatile("cp.async.commit_group;");

    for (int kt = 0; kt < NKT; kt++) {
        __syncthreads();  // all warps done with buffer (kt+1)&1 from iter kt-1
        if (kt + 1 < NKT) { PREFETCH((kt + 1) & 1, (kt + 1) * BK); }
        asm volatile("cp.async.commit_group;");
        asm volatile("cp.async.wait_group 1;");  // tile kt landed
        __syncthreads();

        const __half* sAb = sA[kt & 1];
        const __half* sBb = sB[kt & 1];

#pragma unroll
        for (int ks = 0; ks < BK; ks += 16) {
            // A fragments: 2 x m16k16 via ldmatrix.x4
            uint32_t a[2][4];
#pragma unroll
            for (int mi = 0; mi < 2; mi++) {
                int row = warp_m * 32 + mi * 16 + (lane & 15);
                int col = ks + ((lane >> 4) << 3);
                uint32_t addr = (uint32_t)__cvta_generic_to_shared(&sAb[row * PITCH + col]);
                asm volatile(
                    "ldmatrix.sync.aligned.m8n8.x4.shared.b16 {%0,%1,%2,%3}, [%4];"
                    : "=r"(a[mi][0]), "=r"(a[mi][1]), "=r"(a[mi][2]), "=r"(a[mi][3])
                    : "r"(addr));
            }
            // B fragments: 8 x k16n8; one ldmatrix.x4 covers two adjacent n8 tiles
            uint32_t b[8][2];
#pragma unroll
            for (int nj = 0; nj < 4; nj++) {
                int r = warp_n * 64 + nj * 16 + (lane & 7) + ((lane >> 4) << 3);
                int c = ks + (((lane >> 3) & 1) << 3);
                uint32_t addr = (uint32_t)__cvta_generic_to_shared(&sBb[r * PITCH + c]);
                asm volatile(
                    "ldmatrix.sync.aligned.m8n8.x4.shared.b16 {%0,%1,%2,%3}, [%4];"
                    : "=r"(b[2 * nj][0]), "=r"(b[2 * nj][1]),
                      "=r"(b[2 * nj + 1][0]), "=r"(b[2 * nj + 1][1])
                    : "r"(addr));
            }
#pragma unroll
            for (int mi = 0; mi < 2; mi++)
#pragma unroll
                for (int ni = 0; ni < 8; ni++) MMA_16816(acc[mi][ni], a[mi], b[ni]);
        }
    }

    // Epilogue: add bias, store fp32
    const int orow  = bm + warp_m * 32 + (lane >> 2);
    const int ocol0 = bn + warp_n * 64 + (lane & 3) * 2;
#pragma unroll
    for (int mi = 0; mi < 2; mi++) {
#pragma unroll
        for (int ni = 0; ni < 8; ni++) {
            int r = orow + mi * 16;
            int c = ocol0 + ni * 8;
            float b0 = bias[c];
            float b1 = bias[c + 1];
            float2 v;
            v.x = acc[mi][ni][0] + b0;
            v.y = acc[mi][ni][1] + b1;
            *reinterpret_cast<float2*>(out + (size_t)r * N_OUT + c) = v;
            v.x = acc[mi][ni][2] + b0;
            v.y = acc[mi][ni][3] + b1;
            *reinterpret_cast<float2*>(out + (size_t)(r + 8) * N_OUT + c) = v;
        }
    }
#undef PREFETCH
}

// ---------------------------------------------------------------------------
// Launch
// ---------------------------------------------------------------------------
extern "C" void kernel_launch(void* const* d_in, const int* in_sizes, int n_in,
                              void* d_out, int out_size) {
    const float* x    = (const float*)d_in[0];  // [32768, 1024]
    const float* w    = (const float*)d_in[1];  // [1024, 1024]
    const float* bias = (const float*)d_in[2];  // [1024]
    float* out = (float*)d_out;

    // x -> fp16: 33554432 elems, 4/thread
    convert_x_kernel<<<(M_TOK * (size_t)K_IN) / (256 * 4), 256>>>(x);
    // sign(W) -> fp16: 1048576 elems, 4/thread
    convert_w_kernel<<<((size_t)N_OUT * K_IN) / (256 * 4), 256>>>(w);

    // grid: n-tiles fastest so 8 CTAs sharing an A stripe run adjacently (L2 reuse)
    dim3 grid(N_OUT / BN, M_TOK / BM);  // (8, 256)
    gemm_kernel<<<grid, 256>>>(bias, out);
}

// round 7
// speedup vs baseline: 1.0004x; 1.0004x over previous
#include <cuda_runtime.h>
#include <cuda_fp16.h>
#include <cstdint>
#include <cstddef>

// BinaryLinear: y = x @ sign(W)^T + b
//   x: [32768, 1024] f32, W: [1024, 1024] f32, b: [1024] f32, y: [32768, 1024] f32
// Strategy: sign(W) in {-1,0,+1} is exact in fp16; convert x -> fp16 (rel err ~2.8e-4
// accumulated, safely < 1e-3), then fp16 tensor-core GEMM with fp32 accumulate.

static constexpr int M_TOK = 32768;
static constexpr int N_OUT = 1024;
static constexpr int K_IN  = 1024;

static constexpr int BM = 128, BN = 128, BK = 32;
static constexpr int PITCH = 40;             // halves per smem row (80B) -> conflict-free ldmatrix
static constexpr int NKT = K_IN / BK;        // 32 k-tiles

// Scratch (allocation-free workaround): fp16 x and fp16 sign(W)
__device__ __half g_xh[(size_t)M_TOK * K_IN];   // 64 MB
__device__ __half g_ws[(size_t)N_OUT * K_IN];   // 2 MB

// ---------------------------------------------------------------------------
// Conversion kernels
// ---------------------------------------------------------------------------
__global__ void convert_x_kernel(const float* __restrict__ x) {
    size_t i = ((size_t)blockIdx.x * blockDim.x + threadIdx.x) * 4;
    float4 v = *reinterpret_cast<const float4*>(x + i);
    __half2* dst = reinterpret_cast<__half2*>(g_xh + i);
    dst[0] = __floats2half2_rn(v.x, v.y);
    dst[1] = __floats2half2_rn(v.z, v.w);
}

__global__ void convert_w_kernel(const float* __restrict__ w) {
    size_t i = ((size_t)blockIdx.x * blockDim.x + threadIdx.x) * 4;
    float4 v = *reinterpret_cast<const float4*>(w + i);
    float s0 = (float)((v.x > 0.f) - (v.x < 0.f));
    float s1 = (float)((v.y > 0.f) - (v.y < 0.f));
    float s2 = (float)((v.z > 0.f) - (v.z < 0.f));
    float s3 = (float)((v.w > 0.f) - (v.w < 0.f));
    __half2* dst = reinterpret_cast<__half2*>(g_ws + i);
    dst[0] = __floats2half2_rn(s0, s1);
    dst[1] = __floats2half2_rn(s2, s3);
}

// ---------------------------------------------------------------------------
// GEMM kernel: 128x128x32 CTA tile, 8 warps (4x2), warp tile 32x64,
// mma.sync.m16n8k16 f16->f32, cp.async double buffer.
// ---------------------------------------------------------------------------
__device__ __forceinline__ void cp_async16(uint32_t smem, const void* gmem) {
    asm volatile("cp.async.cg.shared.global [%0], [%1], 16;" :: "r"(smem), "l"(gmem));
}

#define MMA_16816(d, a, b)                                                    \
    asm volatile(                                                             \
        "mma.sync.aligned.m16n8k16.row.col.f32.f16.f16.f32 "                  \
        "{%0,%1,%2,%3}, {%4,%5,%6,%7}, {%8,%9}, {%0,%1,%2,%3};"               \
        : "+f"((d)[0]), "+f"((d)[1]), "+f"((d)[2]), "+f"((d)[3])              \
        : "r"((a)[0]), "r"((a)[1]), "r"((a)[2]), "r"((a)[3]),                 \
          "r"((b)[0]), "r"((b)[1]))

__global__ __launch_bounds__(256, 2)
void gemm_kernel(const float* __restrict__ bias, float* __restrict__ out) {
    __shared__ __half sA[2][BM * PITCH];
    __shared__ __half sB[2][BN * PITCH];

    const int tid    = threadIdx.x;
    const int lane   = tid & 31;
    const int warp   = tid >> 5;
    const int warp_m = warp & 3;   // 4 warps along M
    const int warp_n = warp >> 2;  // 2 warps along N
    const int bm = blockIdx.y * BM;
    const int bn = blockIdx.x * BN;

    const __half* gA = g_xh + (size_t)bm * K_IN;
    const __half* gB = g_ws + (size_t)bn * K_IN;

    // Global->smem load mapping: 512 chunks of 16B (128 rows x 4 chunks),
    // each thread moves 2 chunks for A and 2 for B.
    const int c0 = tid,       r0 = c0 >> 2, col0 = (c0 & 3) * 8;
    const int c1 = tid + 256, r1 = c1 >> 2, col1 = (c1 & 3) * 8;

    float acc[2][8][4];
#pragma unroll
    for (int mi = 0; mi < 2; mi++)
#pragma unroll
        for (int ni = 0; ni < 8; ni++)
#pragma unroll
            for (int q = 0; q < 4; q++) acc[mi][ni][q] = 0.f;

#define PREFETCH(buf, k0)                                                                      \
    do {                                                                                       \
        cp_async16((uint32_t)__cvta_generic_to_shared(&sA[buf][r0 * PITCH + col0]),            \
                   gA + (size_t)r0 * K_IN + (k0) + col0);                                      \
        cp_async16((uint32_t)__cvta_generic_to_shared(&sA[buf][r1 * PITCH + col1]),            \
                   gA + (size_t)r1 * K_IN + (k0) + col1);                                      \
        cp_async16((uint32_t)__cvta_generic_to_shared(&sB[buf][r0 * PITCH + col0]),            \
                   gB + (size_t)r0 * K_IN + (k0) + col0);                                      \
        cp_async16((uint32_t)__cvta_generic_to_shared(&sB[buf][r1 * PITCH + col1]),            \
                   gB + (size_t)r1 * K_IN + (k0) + col1);                                      \
    } while (0)

    PREFETCH(0, 0);
    asm volatile("cp.async.commit_group;");

    for (int kt = 0; kt < NKT; kt++) {
        __syncthreads();  // all warps done with buffer (kt+1)&1 from iter kt-1
        if (kt + 1 < NKT) { PREFETCH((kt + 1) & 1, (kt + 1) * BK); }
        asm volatile("cp.async.commit_group;");
        asm volatile("cp.async.wait_group 1;");  // tile kt landed
        __syncthreads();

        const __half* sAb = sA[kt & 1];
        const __half* sBb = sB[kt & 1];

#pragma unroll
        for (int ks = 0; ks < BK; ks += 16) {
            // A fragments: 2 x m16k16 via ldmatrix.x4
            uint32_t a[2][4];
#pragma unroll
            for (int mi = 0; mi < 2; mi++) {
                int row = warp_m * 32 + mi * 16 + (lane & 15);
                int col = ks + ((lane >> 4) << 3);
                uint32_t addr = (uint32_t)__cvta_generic_to_shared(&sAb[row * PITCH + col]);
                asm volatile(
                    "ldmatrix.sync.aligned.m8n8.x4.shared.b16 {%0,%1,%2,%3}, [%4];"
                    : "=r"(a[mi][0]), "=r"(a[mi][1]), "=r"(a[mi][2]), "=r"(a[mi][3])
                    : "r"(addr));
            }
            // B fragments: 8 x k16n8; one ldmatrix.x4 covers two adjacent n8 tiles
            uint32_t b[8][2];
#pragma unroll
            for (int nj = 0; nj < 4; nj++) {
                int r = warp_n * 64 + nj * 16 + (lane & 7) + ((lane >> 4) << 3);
                int c = ks + (((lane >> 3) & 1) << 3);
                uint32_t addr = (uint32_t)__cvta_generic_to_shared(&sBb[r * PITCH + c]);
                asm volatile(
                    "ldmatrix.sync.aligned.m8n8.x4.shared.b16 {%0,%1,%2,%3}, [%4];"
                    : "=r"(b[2 * nj][0]), "=r"(b[2 * nj][1]),
                      "=r"(b[2 * nj + 1][0]), "=r"(b[2 * nj + 1][1])
                    : "r"(addr));
            }
#pragma unroll
            for (int mi = 0; mi < 2; mi++)
#pragma unroll
                for (int ni = 0; ni < 8; ni++) MMA_16816(acc[mi][ni], a[mi], b[ni]);
        }
    }

    // Epilogue: add bias, store fp32
    const int orow  = bm + warp_m * 32 + (lane >> 2);
    const int ocol0 = bn + warp_n * 64 + (lane & 3) * 2;
#pragma unroll
    for (int mi = 0; mi < 2; mi++) {
#pragma unroll
        for (int ni = 0; ni < 8; ni++) {
            int r = orow + mi * 16;
            int c = ocol0 + ni * 8;
            float b0 = bias[c];
            float b1 = bias[c + 1];
            float2 v;
            v.x = acc[mi][ni][0] + b0;
            v.y = acc[mi][ni][1] + b1;
            *reinterpret_cast<float2*>(out + (size_t)r * N_OUT + c) = v;
            v.x = acc[mi][ni][2] + b0;
            v.y = acc[mi][ni][3] + b1;
            *reinterpret_cast<float2*>(out + (size_t)(r + 8) * N_OUT + c) = v;
        }
    }
#undef PREFETCH
}

// ---------------------------------------------------------------------------
// Launch
// ---------------------------------------------------------------------------
extern "C" void kernel_launch(void* const* d_in, const int* in_sizes, int n_in,
                              void* d_out, int out_size) {
    const float* x    = (const float*)d_in[0];  // [32768, 1024]
    const float* w    = (const float*)d_in[1];  // [1024, 1024]
    const float* bias = (const float*)d_in[2];  // [1024]
    float* out = (float*)d_out;

    // x -> fp16: 33554432 elems, 4/thread
    convert_x_kernel<<<(M_TOK * (size_t)K_IN) / (256 * 4), 256>>>(x);
    // sign(W) -> fp16: 1048576 elems, 4/thread
    convert_w_kernel<<<((size_t)N_OUT * K_IN) / (256 * 4), 256>>>(w);

    // grid: n-tiles fastest so 8 CTAs sharing an A stripe run adjacently (L2 reuse)
    dim3 grid(N_OUT / BN, M_TOK / BM);  // (8, 256)
    gemm_kernel<<<grid, 256>>>(bias, out);
}